// round 6
// baseline (speedup 1.0000x reference)
#include <cuda_runtime.h>
#include <cuda_bf16.h>

// y[i] = dot(x[i, 0:32], w[0:32]) + w[32]
// 256-bit loads: each lane loads 8 consecutive floats (32B) -> 4 lanes per
// row, 8 rows per warp-load-instruction (1KB contiguous per LDG.256).
// Each warp handles 64 rows: 8 front-batched v8 loads, then per-load dot of
// 8 elems + 2-shfl butterfly within 4-lane groups, register transpose, and
// two coalesced 128B stores.

__device__ __forceinline__ void ldg256_cs(const float* p,
                                          float& r0, float& r1, float& r2, float& r3,
                                          float& r4, float& r5, float& r6, float& r7)
{
    asm volatile("ld.global.cs.v8.f32 {%0,%1,%2,%3,%4,%5,%6,%7}, [%8];"
                 : "=f"(r0), "=f"(r1), "=f"(r2), "=f"(r3),
                   "=f"(r4), "=f"(r5), "=f"(r6), "=f"(r7)
                 : "l"(p));
}

__global__ void __launch_bounds__(256, 3)
linreg_kernel(const float* __restrict__ x,
              const float* __restrict__ w,
              float*       __restrict__ y,
              int n)
{
    const int lane = threadIdx.x & 31;

    const int warp = blockIdx.x * (blockDim.x >> 5) + (threadIdx.x >> 5);
    const int row0 = warp << 6;                 // 64 rows per warp
    if (row0 >= n) return;

    // weights: lane's chunk = (lane&3)*8 .. +7 ; bias broadcast
    const float4* w4 = reinterpret_cast<const float4*>(w);
    const float4 wlo = __ldg(w4 + ((lane & 3) << 1));
    const float4 whi = __ldg(w4 + ((lane & 3) << 1) + 1);
    const float bias = __ldg(w + 32);

    // lane address: row (lane>>2) within each 8-row slab, chunk (lane&3)
    const float* base = x + (size_t)row0 * 32 + (size_t)(lane >> 2) * 32
                          + (size_t)(lane & 3) * 8;

    // ---- all 8 x 256-bit loads in flight before any consumer ----
    float a00,a01,a02,a03,a04,a05,a06,a07;
    float a10,a11,a12,a13,a14,a15,a16,a17;
    float a20,a21,a22,a23,a24,a25,a26,a27;
    float a30,a31,a32,a33,a34,a35,a36,a37;
    float b00,b01,b02,b03,b04,b05,b06,b07;
    float b10,b11,b12,b13,b14,b15,b16,b17;
    float b20,b21,b22,b23,b24,b25,b26,b27;
    float b30,b31,b32,b33,b34,b35,b36,b37;
    ldg256_cs(base + 0 * 256, a00,a01,a02,a03,a04,a05,a06,a07);
    ldg256_cs(base + 1 * 256, a10,a11,a12,a13,a14,a15,a16,a17);
    ldg256_cs(base + 2 * 256, a20,a21,a22,a23,a24,a25,a26,a27);
    ldg256_cs(base + 3 * 256, a30,a31,a32,a33,a34,a35,a36,a37);
    ldg256_cs(base + 4 * 256, b00,b01,b02,b03,b04,b05,b06,b07);
    ldg256_cs(base + 5 * 256, b10,b11,b12,b13,b14,b15,b16,b17);
    ldg256_cs(base + 6 * 256, b20,b21,b22,b23,b24,b25,b26,b27);
    ldg256_cs(base + 7 * 256, b30,b31,b32,b33,b34,b35,b36,b37);

    // dot of 8 elems (two independent fma chains) + 2-shfl butterfly
#define DOT_RED(S, E0,E1,E2,E3,E4,E5,E6,E7)                                    \
    float S;                                                                   \
    {                                                                          \
        float p = fmaf(E0, wlo.x, fmaf(E1, wlo.y, fmaf(E2, wlo.z, E3 * wlo.w)));\
        float q = fmaf(E4, whi.x, fmaf(E5, whi.y, fmaf(E6, whi.z, E7 * whi.w)));\
        S = p + q;                                                             \
        S += __shfl_xor_sync(0xffffffffu, S, 2);                               \
        S += __shfl_xor_sync(0xffffffffu, S, 1);                               \
    }

    DOT_RED(s0, a00,a01,a02,a03,a04,a05,a06,a07)
    DOT_RED(s1, a10,a11,a12,a13,a14,a15,a16,a17)
    DOT_RED(s2, a20,a21,a22,a23,a24,a25,a26,a27)
    DOT_RED(s3, a30,a31,a32,a33,a34,a35,a36,a37)
    DOT_RED(s4, b00,b01,b02,b03,b04,b05,b06,b07)
    DOT_RED(s5, b10,b11,b12,b13,b14,b15,b16,b17)
    DOT_RED(s6, b20,b21,b22,b23,b24,b25,b26,b27)
    DOT_RED(s7, b30,b31,b32,b33,b34,b35,b36,b37)
#undef DOT_RED

    // Transpose: lane t wants row t of the block. Load j covers rows
    // j*8 + (u>>2); source lane u = (t&7)*4 + (t>>3), which exports s[u&3]
    // with u&3 == t>>3 == j.  (t>>3 <= 3 within a 32-row block.)
    const int sel = lane & 3;
    const int src = ((lane & 7) << 2) | (lane >> 3);

    // ---- block A: rows row0 .. row0+31 (loads 0..3) ----
    {
        float val = s0;
        val = (sel == 1) ? s1 : val;
        val = (sel == 2) ? s2 : val;
        val = (sel == 3) ? s3 : val;
        float out = __shfl_sync(0xffffffffu, val, src) + bias;
        __stcs(y + row0 + lane, out);
    }
    // ---- block B: rows row0+32 .. row0+63 (loads 4..7) ----
    {
        float val = s4;
        val = (sel == 1) ? s5 : val;
        val = (sel == 2) ? s6 : val;
        val = (sel == 3) ? s7 : val;
        float out = __shfl_sync(0xffffffffu, val, src) + bias;
        __stcs(y + row0 + 32 + lane, out);
    }
}

extern "C" void kernel_launch(void* const* d_in, const int* in_sizes, int n_in,
                              void* d_out, int out_size)
{
    const float* x = (const float*)d_in[0];   // [N, 32] fp32
    const float* w = (const float*)d_in[1];   // [33, 1] fp32
    float* y = (float*)d_out;                 // [N] fp32

    const int n = in_sizes[0] / 32;           // rows
    const int threads = 256;                  // 8 warps -> 512 rows per block
    const int rows_per_block = (threads / 32) * 64;
    const int blocks = (n + rows_per_block - 1) / rows_per_block;
    linreg_kernel<<<blocks, threads>>>(x, w, y, n);
}

// round 7
// speedup vs baseline: 1.0074x; 1.0074x over previous
#include <cuda_runtime.h>
#include <cuda_bf16.h>

// y[i] = dot(x[i, 0:32], w[0:32]) + w[32]
// One-shot warps: each warp handles 64 rows (2 blocks of 32). All 16
// coalesced streaming LDG.128 (8 KB) issued before any consumer, then the two
// blocks are reduced (3x shfl_xor butterfly per 8-lane group), transposed via
// one shfl, and stored as two coalesced 128B *cached* stores (y stays in L2,
// writeback deferred past the read stream -> no in-kernel RW turnaround).
__global__ void __launch_bounds__(256, 3)
linreg_kernel(const float4* __restrict__ x4,
              const float*  __restrict__ w,
              float*        __restrict__ y,
              int n)
{
    const int lane = threadIdx.x & 31;
    const int lig  = lane & 7;

    const int warp = blockIdx.x * (blockDim.x >> 5) + (threadIdx.x >> 5);
    const int row0 = warp << 6;                 // 64 rows per warp
    if (row0 >= n) return;

    const float4 wv  = __ldg(reinterpret_cast<const float4*>(w) + lig);
    const float bias = __ldg(w + 32);

    const float4* base = x4 + (size_t)row0 * 8 + lane;

    // ---- all 16 loads in flight before any consumer ----
    float4 a0 = __ldcs(base +  0 * 32);
    float4 a1 = __ldcs(base +  1 * 32);
    float4 a2 = __ldcs(base +  2 * 32);
    float4 a3 = __ldcs(base +  3 * 32);
    float4 a4 = __ldcs(base +  4 * 32);
    float4 a5 = __ldcs(base +  5 * 32);
    float4 a6 = __ldcs(base +  6 * 32);
    float4 a7 = __ldcs(base +  7 * 32);
    float4 b0 = __ldcs(base +  8 * 32);
    float4 b1 = __ldcs(base +  9 * 32);
    float4 b2 = __ldcs(base + 10 * 32);
    float4 b3 = __ldcs(base + 11 * 32);
    float4 b4 = __ldcs(base + 12 * 32);
    float4 b5 = __ldcs(base + 13 * 32);
    float4 b6 = __ldcs(base + 14 * 32);
    float4 b7 = __ldcs(base + 15 * 32);

#define DOT_RED(S, V)                                                          \
    float S = fmaf((V).x, wv.x,                                                \
              fmaf((V).y, wv.y, fmaf((V).z, wv.z, (V).w * wv.w)));             \
    S += __shfl_xor_sync(0xffffffffu, S, 4);                                   \
    S += __shfl_xor_sync(0xffffffffu, S, 2);                                   \
    S += __shfl_xor_sync(0xffffffffu, S, 1);

    const int src = ((lane & 3) << 3) | (lane >> 2);  // transpose source lane

    // ---- block A: rows row0 .. row0+31 ----
    {
        DOT_RED(s0, a0) DOT_RED(s1, a1) DOT_RED(s2, a2) DOT_RED(s3, a3)
        DOT_RED(s4, a4) DOT_RED(s5, a5) DOT_RED(s6, a6) DOT_RED(s7, a7)
        float val = s0;
        val = (lig == 1) ? s1 : val;
        val = (lig == 2) ? s2 : val;
        val = (lig == 3) ? s3 : val;
        val = (lig == 4) ? s4 : val;
        val = (lig == 5) ? s5 : val;
        val = (lig == 6) ? s6 : val;
        val = (lig == 7) ? s7 : val;
        float out = __shfl_sync(0xffffffffu, val, src) + bias;
        y[row0 + lane] = out;                 // cached store, L2-resident
    }
    // ---- block B: rows row0+32 .. row0+63 ----
    {
        DOT_RED(s0, b0) DOT_RED(s1, b1) DOT_RED(s2, b2) DOT_RED(s3, b3)
        DOT_RED(s4, b4) DOT_RED(s5, b5) DOT_RED(s6, b6) DOT_RED(s7, b7)
        float val = s0;
        val = (lig == 1) ? s1 : val;
        val = (lig == 2) ? s2 : val;
        val = (lig == 3) ? s3 : val;
        val = (lig == 4) ? s4 : val;
        val = (lig == 5) ? s5 : val;
        val = (lig == 6) ? s6 : val;
        val = (lig == 7) ? s7 : val;
        float out = __shfl_sync(0xffffffffu, val, src) + bias;
        y[row0 + 32 + lane] = out;            // cached store, L2-resident
    }
#undef DOT_RED
}

extern "C" void kernel_launch(void* const* d_in, const int* in_sizes, int n_in,
                              void* d_out, int out_size)
{
    const float* x = (const float*)d_in[0];   // [N, 32] fp32
    const float* w = (const float*)d_in[1];   // [33, 1] fp32
    float* y = (float*)d_out;                 // [N] fp32

    const int n = in_sizes[0] / 32;           // rows
    const int threads = 256;                  // 8 warps -> 512 rows per block
    const int rows_per_block = (threads / 32) * 64;
    const int blocks = (n + rows_per_block - 1) / rows_per_block;
    linreg_kernel<<<blocks, threads>>>(
        reinterpret_cast<const float4*>(x), w, y, n);
}